// round 13
// baseline (speedup 1.0000x reference)
#include <cuda_runtime.h>
#include <cuda_fp16.h>
#include <cstdint>

#define NMAX 10000
#define H1 4
#define C 128
#define F1 512
#define ELLW 256
#define GCAP 128
#define MTILE 64
#define BPAD 520        // padded row stride in halves (512+8): conflict-free frags

// dynamic smem offsets (bytes)
#define AS_OFF   0                         // 64*520*2  = 66560
#define BS_OFF   66560                     // 128*520*2 = 133120
#define W0_OFF   199680                    // 512 f
#define W1_OFF   201728
#define B1_OFF   203776
#define ASW_OFF  205824                    // 128 f
#define ADW_OFF  206336
#define SMEM_DYN 206848

// ---------------- scratch ----------------
__device__ int      g_is64;
__device__ int      g_cur[NMAX];
__device__ int      g_ell[NMAX * ELLW];
__device__ float    g_c[16];
__device__ __align__(16) float g_a0[NMAX * 4];
__device__ __align__(16) float g_a1[NMAX * 4];
__device__ __align__(16) __half g_w2h[C * F1];    // [ch][k] fp16 W2^T
__device__ __align__(16) __half2 g_h2h[NMAX * (C / 2)];
__device__ float g_as2[NMAX];
__device__ float g_ad2[NMAX];

__device__ __forceinline__ float lrelu(float v) { return v > 0.f ? v : 0.2f * v; }

// ---------------- setup: ELL init + rank-2 constants + W2->fp16 + dtype ----------------
__global__ void setup_kernel(const int* __restrict__ ei32, const float* __restrict__ W1,
                             const float* __restrict__ asw, const float* __restrict__ adw,
                             const float* __restrict__ W2, int n, int nthreads) {
    int i = blockIdx.x * blockDim.x + threadIdx.x;
    if (i < n) {
        g_cur[i] = 1;
        g_ell[i * ELLW] = i;
    }
    // W2 -> g_w2h transpose+convert (coalesced reads)
    for (int idx = i; idx < F1 * C; idx += nthreads) {
        int k = idx >> 7, ch = idx & 127;
        g_w2h[ch * F1 + k] = __float2half(W2[idx]);
    }
    if (blockIdx.x == 0) {
        int t = threadIdx.x;
        if (t < 128) {
            int h = t >> 5, lane = t & 31;
            float cs0 = 0.f, cs1 = 0.f, cd0 = 0.f, cd1 = 0.f;
#pragma unroll
            for (int q = 0; q < 4; q++) {
                int f = h * C + lane + 32 * q;
                float w0 = W1[f], w1 = W1[F1 + f];
                float as = asw[f], ad = adw[f];
                cs0 += w0 * as; cs1 += w1 * as;
                cd0 += w0 * ad; cd1 += w1 * ad;
            }
#pragma unroll
            for (int o = 16; o > 0; o >>= 1) {
                cs0 += __shfl_down_sync(0xFFFFFFFFu, cs0, o);
                cs1 += __shfl_down_sync(0xFFFFFFFFu, cs1, o);
                cd0 += __shfl_down_sync(0xFFFFFFFFu, cd0, o);
                cd1 += __shfl_down_sync(0xFFFFFFFFu, cd1, o);
            }
            if (lane == 0) {
                g_c[h] = cs0; g_c[4 + h] = cs1; g_c[8 + h] = cd0; g_c[12 + h] = cd1;
            }
        } else if (t == 128) {
            int allzero = 1;
            for (int k = 1; k < 128; k += 2)
                if (ei32[k] != 0) { allzero = 0; break; }
            g_is64 = allzero;
        }
    }
}

// ---------------- scatter: 4 edges per thread ----------------
__global__ void scatter_kernel(const int* __restrict__ ei32, int e) {
    int i0 = (blockIdx.x * blockDim.x + threadIdx.x) * 4;
    if (i0 >= e) return;
    int cnt = min(4, e - i0);
    int src[4], dst[4];
    if (g_is64) {
        const long long* e64 = (const long long*)ei32;
#pragma unroll
        for (int k = 0; k < 4; k++)
            if (k < cnt) { src[k] = (int)e64[i0 + k]; dst[k] = (int)e64[e + i0 + k]; }
    } else {
#pragma unroll
        for (int k = 0; k < 4; k++)
            if (k < cnt) { src[k] = ei32[i0 + k]; dst[k] = ei32[e + i0 + k]; }
    }
#pragma unroll
    for (int k = 0; k < 4; k++) {
        if (k < cnt) {
            int pos = atomicAdd(&g_cur[dst[k]], 1);
            if (pos < ELLW) g_ell[dst[k] * ELLW + pos] = src[k];
        }
    }
}

// ---------------- layer 1: 8-lanes-per-node rank-2 GAT ----------------
__global__ void __launch_bounds__(256) gat1_kernel(const float* __restrict__ x, int n) {
    __shared__ float cs[16];
    int tid = threadIdx.x;
    if (tid < 16) cs[tid] = g_c[tid];
    __syncthreads();
    int w = tid >> 5, lane = tid & 31;
    int oct = lane >> 3, ol = lane & 7;
    int node = blockIdx.x * 32 + w * 4 + oct;
    bool valid = node < n;

    int deg = 0;
    const int* row = g_ell;
    float xd0 = 0.f, xd1 = 0.f;
    if (valid) {
        deg = min(g_cur[node], ELLW);
        row = g_ell + node * ELLW;
        float2 xv = *reinterpret_cast<const float2*>(x + 2 * node);
        xd0 = xv.x; xd1 = xv.y;
    }
    float dh[H1];
#pragma unroll
    for (int h = 0; h < H1; h++) dh[h] = xd0 * cs[8 + h] + xd1 * cs[12 + h];

    float sp[H1] = {0.f, 0.f, 0.f, 0.f};
    float s0[H1] = {0.f, 0.f, 0.f, 0.f};
    float s1[H1] = {0.f, 0.f, 0.f, 0.f};
    for (int j = ol; j < deg; j += 8) {
        int src = row[j];
        float2 xs = *reinterpret_cast<const float2*>(x + 2 * src);
#pragma unroll
        for (int h = 0; h < H1; h++) {
            float e = lrelu(fmaf(xs.x, cs[h], fmaf(xs.y, cs[4 + h], dh[h])));
            float p = __expf(e);
            sp[h] += p;
            s0[h] += p * xs.x;
            s1[h] += p * xs.y;
        }
    }
#pragma unroll
    for (int o = 4; o > 0; o >>= 1) {
#pragma unroll
        for (int h = 0; h < H1; h++) {
            sp[h] += __shfl_down_sync(0xFFFFFFFFu, sp[h], o, 8);
            s0[h] += __shfl_down_sync(0xFFFFFFFFu, s0[h], o, 8);
            s1[h] += __shfl_down_sync(0xFFFFFFFFu, s1[h], o, 8);
        }
    }
    if (ol == 0 && valid) {
        float4 a0, a1;
        float i0 = 1.f / (sp[0] + 1e-16f);
        float i1 = 1.f / (sp[1] + 1e-16f);
        float i2 = 1.f / (sp[2] + 1e-16f);
        float i3 = 1.f / (sp[3] + 1e-16f);
        a0.x = s0[0] * i0; a0.y = s0[1] * i1; a0.z = s0[2] * i2; a0.w = s0[3] * i3;
        a1.x = s1[0] * i0; a1.y = s1[1] * i1; a1.z = s1[2] * i2; a1.w = s1[3] * i3;
        ((float4*)g_a0)[node] = a0;
        ((float4*)g_a1)[node] = a1;
    }
}

// ---------------- layer 2 GEMM: mma.sync m16n8k16, M=64 N=128 K=512, one sync ----------------
__global__ void __launch_bounds__(256) gemm2_mma(const float* __restrict__ asw,
                            const float* __restrict__ adw,
                            const float* __restrict__ W1, const float* __restrict__ b1,
                            int n) {
    extern __shared__ char dsm[];
    __half* As = (__half*)(dsm + AS_OFF);
    __half* Bs = (__half*)(dsm + BS_OFF);
    float* w0s = (float*)(dsm + W0_OFF);
    float* w1s = (float*)(dsm + W1_OFF);
    float* b1s = (float*)(dsm + B1_OFF);
    float* asw_s = (float*)(dsm + ASW_OFF);
    float* adw_s = (float*)(dsm + ADW_OFF);
    __shared__ float s_as[2][MTILE], s_ad[2][MTILE];

    int tid = threadIdx.x;
    int w = tid >> 5, lane = tid & 31;
    int wm = w & 3, wn = w >> 2;
    int g = lane >> 2, tg = lane & 3;
    int base = blockIdx.x * MTILE;

    // stage constants
    w0s[tid] = W1[tid];        w0s[tid + 256] = W1[tid + 256];
    w1s[tid] = W1[F1 + tid];   w1s[tid + 256] = W1[F1 + tid + 256];
    b1s[tid] = b1[tid];        b1s[tid + 256] = b1[tid + 256];
    if (tid < C) { asw_s[tid] = asw[tid]; adw_s[tid] = adw[tid]; }

    // stage B: full W2^T fp16 (uint4 copies from g_w2h)
    {
        const uint4* src = (const uint4*)g_w2h;     // 64 uint4 per ch row
        for (int idx = tid; idx < C * 64; idx += 256) {
            int ch = idx >> 6, kq = idx & 63;
            *reinterpret_cast<uint4*>(&Bs[ch * BPAD + kq * 8]) = src[ch * 64 + kq];
        }
    }
    __syncthreads();   // w0s/w1s/b1s ready for A staging

    // stage A: full rank-2 out1 tile fp16. thread owns row m=tid>>2, head=tid&3
    {
        int m = tid >> 2, head = tid & 3;
        int node = base + m;
        float A0 = 0.f, A1 = 0.f;
        if (node < n) {
            A0 = g_a0[node * 4 + head];
            A1 = g_a1[node * 4 + head];
        }
        int kb = head * 128;
#pragma unroll 8
        for (int t2 = 0; t2 < 64; t2++) {
            int k = kb + 2 * t2;
            float v0 = fmaxf(fmaf(A0, w0s[k],     fmaf(A1, w1s[k],     b1s[k])),     0.f);
            float v1 = fmaxf(fmaf(A0, w0s[k + 1], fmaf(A1, w1s[k + 1], b1s[k + 1])), 0.f);
            *reinterpret_cast<__half2*>(&As[m * BPAD + k]) = __floats2half2_rn(v0, v1);
        }
    }
    __syncthreads();   // the ONLY full barrier before epilogue

    // compute: 32 ksteps, 8 n-tiles per warp
    float c[8][4];
#pragma unroll
    for (int nt = 0; nt < 8; nt++) {
        c[nt][0] = 0.f; c[nt][1] = 0.f; c[nt][2] = 0.f; c[nt][3] = 0.f;
    }
    int arow1 = (wm * 16 + g) * BPAD;
    int arow2 = (wm * 16 + 8 + g) * BPAD;
#pragma unroll 4
    for (int ks = 0; ks < 32; ks++) {
        int k0 = ks * 16;
        uint32_t a0 = *reinterpret_cast<const uint32_t*>(&As[arow1 + k0 + 2 * tg]);
        uint32_t a1 = *reinterpret_cast<const uint32_t*>(&As[arow2 + k0 + 2 * tg]);
        uint32_t a2 = *reinterpret_cast<const uint32_t*>(&As[arow1 + k0 + 2 * tg + 8]);
        uint32_t a3 = *reinterpret_cast<const uint32_t*>(&As[arow2 + k0 + 2 * tg + 8]);
#pragma unroll
        for (int nt = 0; nt < 8; nt++) {
            int brow = (wn * 64 + nt * 8 + g) * BPAD;
            uint32_t b0 = *reinterpret_cast<const uint32_t*>(&Bs[brow + k0 + 2 * tg]);
            uint32_t b1r = *reinterpret_cast<const uint32_t*>(&Bs[brow + k0 + 2 * tg + 8]);
            asm volatile(
                "mma.sync.aligned.m16n8k16.row.col.f32.f16.f16.f32 "
                "{%0,%1,%2,%3}, {%4,%5,%6,%7}, {%8,%9}, {%0,%1,%2,%3};"
                : "+f"(c[nt][0]), "+f"(c[nt][1]), "+f"(c[nt][2]), "+f"(c[nt][3])
                : "r"(a0), "r"(a1), "r"(a2), "r"(a3), "r"(b0), "r"(b1r));
        }
    }

    // epilogue: local rows r1l = 16wm+g (c0,c1), r2l = r1l+8 (c2,c3); cols wn*64+nt*8+2tg
    int r1l = wm * 16 + g, r2l = r1l + 8;
    int r1 = base + r1l, r2 = base + r2l;
    float as1v = 0.f, ad1v = 0.f, as2v = 0.f, ad2v = 0.f;
#pragma unroll
    for (int nt = 0; nt < 8; nt++) {
        int col = wn * 64 + nt * 8 + 2 * tg;
        float ws0 = asw_s[col], ws1 = asw_s[col + 1];
        float wd0 = adw_s[col], wd1 = adw_s[col + 1];
        as1v += c[nt][0] * ws0 + c[nt][1] * ws1;
        ad1v += c[nt][0] * wd0 + c[nt][1] * wd1;
        as2v += c[nt][2] * ws0 + c[nt][3] * ws1;
        ad2v += c[nt][2] * wd0 + c[nt][3] * wd1;
        __half2 p1 = __floats2half2_rn(c[nt][0], c[nt][1]);
        __half2 p2 = __floats2half2_rn(c[nt][2], c[nt][3]);
        int hcol = wn * 32 + nt * 4 + tg;
        if (r1 < n) g_h2h[r1 * 64 + hcol] = p1;
        if (r2 < n) g_h2h[r2 * 64 + hcol] = p2;
    }
#pragma unroll
    for (int o = 1; o < 4; o <<= 1) {
        as1v += __shfl_down_sync(0xFFFFFFFFu, as1v, o, 4);
        ad1v += __shfl_down_sync(0xFFFFFFFFu, ad1v, o, 4);
        as2v += __shfl_down_sync(0xFFFFFFFFu, as2v, o, 4);
        ad2v += __shfl_down_sync(0xFFFFFFFFu, ad2v, o, 4);
    }
    if (tg == 0) {
        s_as[wn][r1l] = as1v; s_ad[wn][r1l] = ad1v;
        s_as[wn][r2l] = as2v; s_ad[wn][r2l] = ad2v;
    }
    __syncthreads();
    if (tid < MTILE) {
        int node = base + tid;
        if (node < n) {
            g_as2[node] = s_as[0][tid] + s_as[1][tid];
            g_ad2[node] = s_ad[0][tid] + s_ad[1][tid];
        }
    }
}

// ---------------- layer 2: warp-per-node softmax + fp16 aggregation ----------------
__global__ void __launch_bounds__(256) gat2_kernel(const float* __restrict__ b2,
                            const float* __restrict__ Wp, const float* __restrict__ bp,
                            float* __restrict__ out, int n) {
    __shared__ float s_p[8][GCAP];
    __shared__ int   s_src[8][GCAP];
    int tid = threadIdx.x;
    int w = tid >> 5, lane = tid & 31;
    int node = blockIdx.x * 8 + w;
    if (node >= n) return;

    int deg = min(g_cur[node], ELLW);
    const int* row = g_ell + node * ELLW;
    float ad = g_ad2[node];

    float4 acc = make_float4(0.f, 0.f, 0.f, 0.f);
    float psum = 0.f;
    for (int base = 0; base < deg; base += GCAP) {
        int cnt = min(GCAP, deg - base);
        for (int j = lane; j < cnt; j += 32) {
            int src = row[base + j];
            s_src[w][j] = src;
            float p = __expf(lrelu(g_as2[src] + ad));
            s_p[w][j] = p;
            psum += p;
        }
        __syncwarp();
#pragma unroll 4
        for (int j = 0; j < cnt; j++) {
            int src = s_src[w][j];
            float pj = s_p[w][j];
            uint2 raw = *reinterpret_cast<const uint2*>(&g_h2h[src * 64 + 2 * lane]);
            float2 fa = __half22float2(*reinterpret_cast<__half2*>(&raw.x));
            float2 fb = __half22float2(*reinterpret_cast<__half2*>(&raw.y));
            acc.x += pj * fa.x; acc.y += pj * fa.y;
            acc.z += pj * fb.x; acc.w += pj * fb.y;
        }
        __syncwarp();
    }
#pragma unroll
    for (int o = 16; o > 0; o >>= 1)
        psum += __shfl_xor_sync(0xFFFFFFFFu, psum, o);

    float inv = 1.f / (psum + 1e-16f);
    float4 bq = ((const float4*)b2)[lane];
    float4 wq = ((const float4*)Wp)[lane];
    float o0 = fmaxf(acc.x * inv + bq.x, 0.f);
    float o1 = fmaxf(acc.y * inv + bq.y, 0.f);
    float o2 = fmaxf(acc.z * inv + bq.z, 0.f);
    float o3 = fmaxf(acc.w * inv + bq.w, 0.f);
    float v = o0 * wq.x + o1 * wq.y + o2 * wq.z + o3 * wq.w;
#pragma unroll
    for (int o = 16; o > 0; o >>= 1)
        v += __shfl_down_sync(0xFFFFFFFFu, v, o);
    if (lane == 0) out[node] = v + bp[0];
}

// ---------------- launch ----------------
extern "C" void kernel_launch(void* const* d_in, const int* in_sizes, int n_in,
                              void* d_out, int out_size) {
    const float* x    = (const float*)d_in[0];
    const int*   ei32 = (const int*)d_in[1];
    const float* W1   = (const float*)d_in[2];
    const float* as1w = (const float*)d_in[3];
    const float* ad1w = (const float*)d_in[4];
    const float* b1   = (const float*)d_in[5];
    const float* W2   = (const float*)d_in[6];
    const float* as2w = (const float*)d_in[7];
    const float* ad2w = (const float*)d_in[8];
    const float* b2   = (const float*)d_in[9];
    const float* Wp   = (const float*)d_in[10];
    const float* bp   = (const float*)d_in[11];
    float* out = (float*)d_out;

    int n = in_sizes[0] / 2;
    int e = in_sizes[1] / 2;

    cudaFuncSetAttribute(gemm2_mma, cudaFuncAttributeMaxDynamicSharedMemorySize, SMEM_DYN);

    int nblk = (n + 255) / 256;
    setup_kernel<<<nblk, 256>>>(ei32, W1, as1w, ad1w, W2, n, nblk * 256);
    scatter_kernel<<<(e + 1023) / 1024, 256>>>(ei32, e);

    gat1_kernel<<<(n + 31) / 32, 256>>>(x, n);
    gemm2_mma<<<(n + MTILE - 1) / MTILE, 256, SMEM_DYN>>>(as2w, ad2w, W1, b1, n);
    gat2_kernel<<<(n + 7) / 8, 256>>>(b2, Wp, bp, out, n);
}